// round 15
// baseline (speedup 1.0000x reference)
#include <cuda_runtime.h>
#include <cuda_fp16.h>
#include <cstdint>

// DotReluAttention: out = relu(Q @ K^T / 64) @ V ; B=2,H=8,S=4096,D=64 fp32.
// v12 = v11 + BN=256 (half the barriers/waits) + warp-phase-staggered chunk
// ring (decorrelates LDS/MMA bursts across the 4 warps per SMSP).
// fp16 m16n8k16, 512 threads, BM=256, cp.async double buffering.

#define SEQ 4096
#define HD  64
#define BM  256
#define BN  256
#define NTH 512
#define NITER (SEQ/BN)    // 16
#define NK16  (BN/16)     // 16
#define BH    16

// smem geometry (32-bit words)
#define QSTR 40           // Q staging rows (startup only)
#define KSTR 40           // K rows: 32 data words + 8 pad
#define VSTR 72           // V pair-rows: 64 data words + 8 pad
#define KWORDS (BN*KSTR)              // 10240
#define BUFW   (KWORDS + (BN/2)*VSTR) // 19456 words per buffer
#define SMEM_WORDS (2*BUFW)           // 38912
#define SMEM_BYTES (SMEM_WORDS*4)     // 155648

// pre-converted fp16 images (packed half2 words)
__device__ __align__(16) uint32_t g_K16[(size_t)BH*SEQ*32];       // 8MB
__device__ __align__(16) uint32_t g_V16[(size_t)BH*(SEQ/2)*64];   // 8MB

__device__ __forceinline__ uint32_t pack2(float a, float b) {
    __half2 h = __floats2half2_rn(a, b);
    return *reinterpret_cast<uint32_t*>(&h);
}
__device__ __forceinline__ void mma16(float* c, const uint32_t* a,
                                      uint32_t b0, uint32_t b1) {
    asm volatile(
        "mma.sync.aligned.m16n8k16.row.col.f32.f16.f16.f32 "
        "{%0,%1,%2,%3}, {%4,%5,%6,%7}, {%8,%9}, {%0,%1,%2,%3};\n"
        : "+f"(c[0]), "+f"(c[1]), "+f"(c[2]), "+f"(c[3])
        : "r"(a[0]), "r"(a[1]), "r"(a[2]), "r"(a[3]), "r"(b0), "r"(b1));
}
__device__ __forceinline__ int wpos(int w) {    // pair-permute within 8-word chunk
    return (w & ~7) + 2 * (w & 3) + ((w & 4) >> 2);
}
__device__ __forceinline__ uint32_t smem_u32(const void* p) {
    uint32_t a;
    asm("{ .reg .u64 t; cvta.to.shared.u64 t, %1; cvt.u32.u64 %0, t; }" : "=r"(a) : "l"(p));
    return a;
}

// ---------------- kernel 1: fp32 -> packed fp16 images ----------------
__global__ __launch_bounds__(512)
void convert_kv(const float* __restrict__ K, const float* __restrict__ V) {
    int t = blockIdx.x * 512 + threadIdx.x;   // 0 .. 262143
    {   // K: row-major, wpos-permuted pairs
        int row = t >> 2, j = t & 3;
        const float4* src = (const float4*)(K + (size_t)row * HD + j * 16);
        float4 a = src[0], b = src[1], c = src[2], d = src[3];
        uint32_t* dst = g_K16 + (size_t)row * 32 + j * 8;
        dst[0] = pack2(a.x, a.y); dst[2] = pack2(a.z, a.w);
        dst[4] = pack2(b.x, b.y); dst[6] = pack2(b.z, b.w);
        dst[1] = pack2(c.x, c.y); dst[3] = pack2(c.z, c.w);
        dst[5] = pack2(d.x, d.y); dst[7] = pack2(d.z, d.w);
    }
    {   // V: vertical kv-pair packing: word = {V[2pr][n], V[2pr+1][n]}
        int pr = t >> 3, j = t & 7;
        const float* s0 = V + (size_t)(2 * pr) * HD + j * 8;
        float4 r0a = ((const float4*)s0)[0], r0b = ((const float4*)s0)[1];
        float4 r1a = ((const float4*)(s0 + HD))[0], r1b = ((const float4*)(s0 + HD))[1];
        uint32_t* dst = g_V16 + (size_t)pr * 64 + j * 8;
        dst[0] = pack2(r0a.x, r1a.x); dst[1] = pack2(r0a.y, r1a.y);
        dst[2] = pack2(r0a.z, r1a.z); dst[3] = pack2(r0a.w, r1a.w);
        dst[4] = pack2(r0b.x, r1b.x); dst[5] = pack2(r0b.y, r1b.y);
        dst[6] = pack2(r0b.z, r1b.z); dst[7] = pack2(r0b.w, r1b.w);
    }
}

// issue cp.async copies for one K/V tile into smem buffer at byte addr sbuf
__device__ __forceinline__ void issue_tile(int bh, int it, uint32_t sbuf, int tid) {
    const char* kbase = (const char*)(g_K16 + ((size_t)bh * SEQ + it * BN) * 32);
    #pragma unroll
    for (int i = 0; i < 4; i++) {
        int c = tid + i * NTH;                 // 2048 chunks of 16B
        uint32_t dst = sbuf + (c >> 3) * (KSTR * 4) + (c & 7) * 16;
        asm volatile("cp.async.cg.shared.global [%0], [%1], 16;"
                     :: "r"(dst), "l"(kbase + c * 16) : "memory");
    }
    const char* vbase = (const char*)(g_V16 + ((size_t)bh * (SEQ/2) + it * (BN/2)) * 64);
    uint32_t svbuf = sbuf + KWORDS * 4;
    #pragma unroll
    for (int i = 0; i < 4; i++) {
        int c = tid + i * NTH;                 // 2048 chunks of 16B
        uint32_t dst = svbuf + (c >> 4) * (VSTR * 4) + (c & 15) * 16;
        asm volatile("cp.async.cg.shared.global [%0], [%1], 16;"
                     :: "r"(dst), "l"(vbase + c * 16) : "memory");
    }
}
#define CP_COMMIT() asm volatile("cp.async.commit_group;" ::: "memory")
#define CP_WAIT(n)  asm volatile("cp.async.wait_group %0;" :: "n"(n) : "memory")

// GEMM1 for one 16-col chunk nk: s[0..3] = cols 16nk+0..7, s[4..7] = +8..15
__device__ __forceinline__ void g1_chunk(const uint32_t* sK,
                                         const uint32_t qa[4][4],
                                         int gid, int tig, int nk, float* s) {
    #pragma unroll
    for (int h = 0; h < 2; h++) {
        const uint32_t* kb = &sK[((2 * nk + h) * 8 + gid) * KSTR + 2 * tig];
        uint2 b0 = *(const uint2*)(kb);
        uint2 b1 = *(const uint2*)(kb + 8);
        uint2 b2 = *(const uint2*)(kb + 16);
        uint2 b3 = *(const uint2*)(kb + 24);
        float ta[4] = {0.f, 0.f, 0.f, 0.f};
        float tb[4] = {0.f, 0.f, 0.f, 0.f};
        mma16(ta, qa[0], b0.x, b0.y);
        mma16(tb, qa[1], b1.x, b1.y);
        mma16(ta, qa[2], b2.x, b2.y);
        mma16(tb, qa[3], b3.x, b3.y);
        s[4*h+0] = ta[0] + tb[0]; s[4*h+1] = ta[1] + tb[1];
        s[4*h+2] = ta[2] + tb[2]; s[4*h+3] = ta[3] + tb[3];
    }
}

// ---------------- kernel 2: fused attention ----------------
__global__ __launch_bounds__(NTH, 1)
void dot_relu_attn_v12(const float* __restrict__ Q, float* __restrict__ O) {
    extern __shared__ uint32_t sm[];

    const int tid  = threadIdx.x;
    const int warp = tid >> 5;
    const int lane = tid & 31;
    const int gid  = lane >> 2;
    const int tig  = lane & 3;
    const int m0   = warp * 16;
    const int ph   = ((warp >> 2) & 3) * 4;   // chunk-ring phase per SMSP-mate

    const int bh = blockIdx.y;
    const int qb = blockIdx.x * BM;
    const float* Qp = Q + ((size_t)bh * SEQ + qb) * HD;
    float*       Op = O + ((size_t)bh * SEQ + qb) * HD;

    // ---- Stage Q (one-time; staging overlaps the K/V buffers) ----
    #pragma unroll
    for (int i = 0; i < 8; i++) {
        int lin = tid + i * NTH;
        int row = lin >> 4, c4 = lin & 15;
        float4 v = *(const float4*)(Qp + row * HD + c4 * 4);
        sm[row * QSTR + wpos(2 * c4)]     = pack2(v.x, v.y);
        sm[row * QSTR + wpos(2 * c4 + 1)] = pack2(v.z, v.w);
    }
    __syncthreads();
    uint32_t qa[4][4];
    #pragma unroll
    for (int kt = 0; kt < 4; kt++) {
        const uint32_t* p = &sm[(m0 + gid) * QSTR + kt * 8 + 2 * tig];
        uint2 lo = *(const uint2*)p;
        uint2 hi = *(const uint2*)(p + 8 * QSTR);
        qa[kt][0] = lo.x; qa[kt][1] = hi.x;
        qa[kt][2] = lo.y; qa[kt][3] = hi.y;
    }
    __syncthreads();   // staging done; buffers free

    float oacc[8][4];
    #pragma unroll
    for (int b = 0; b < 8; b++)
        #pragma unroll
        for (int c = 0; c < 4; c++) oacc[b][c] = 0.f;

    // prologue: start tile 0
    issue_tile(bh, 0, smem_u32(sm), tid);
    CP_COMMIT();

    #pragma unroll 1
    for (int it = 0; it < NITER; it++) {
        if (it + 1 < NITER) {
            issue_tile(bh, it + 1, smem_u32(sm) + ((it + 1) & 1) * (BUFW * 4), tid);
            CP_COMMIT();
            CP_WAIT(1);            // tile it has landed
        } else {
            CP_WAIT(0);
        }
        __syncthreads();           // make all threads' copies visible

        const uint32_t* sK = sm + (it & 1) * BUFW;
        const uint32_t* sV = sK + KWORDS;

        // ---- pipelined, phase-staggered chunk ring ----
        float scur[8];
        g1_chunk(sK, qa, gid, tig, ph, scur);
        #pragma unroll 4
        for (int j = 0; j < NK16; j++) {
            const int nk = (j + ph) & (NK16 - 1);
            float snxt[8];
            if (j + 1 < NK16)
                g1_chunk(sK, qa, gid, tig, (j + 1 + ph) & (NK16 - 1), snxt);

            // relu + pack: GEMM1 C-fragment == GEMM2 A-fragment
            uint32_t pa[4];
            pa[0] = pack2(fmaxf(scur[0], 0.f), fmaxf(scur[1], 0.f));
            pa[1] = pack2(fmaxf(scur[2], 0.f), fmaxf(scur[3], 0.f));
            pa[2] = pack2(fmaxf(scur[4], 0.f), fmaxf(scur[5], 0.f));
            pa[3] = pack2(fmaxf(scur[6], 0.f), fmaxf(scur[7], 0.f));

            // GEMM2: B from packed V (2x LDS.32), 8 independent accumulators
            const uint32_t* vb = &sV[(8 * nk + tig) * VSTR + gid];
            #pragma unroll
            for (int n2 = 0; n2 < 8; n2++) {
                uint32_t b0 = vb[n2 * 8];
                uint32_t b1 = vb[4 * VSTR + n2 * 8];
                mma16(oacc[n2], pa, b0, b1);
            }

            #pragma unroll
            for (int x = 0; x < 8; x++) scur[x] = snxt[x];
        }
        __syncthreads();           // done reading buf it&1 before it's rewritten
    }

    // ---- Epilogue: O_out = O / 64 ----
    {
        float* r0 = Op + (size_t)(m0 + gid) * HD;
        float* r1 = r0 + 8 * HD;
        #pragma unroll
        for (int n2 = 0; n2 < 8; n2++) {
            int col = n2 * 8 + 2 * tig;
            *(float2*)(r0 + col) = make_float2(oacc[n2][0] * 0.015625f,
                                               oacc[n2][1] * 0.015625f);
            *(float2*)(r1 + col) = make_float2(oacc[n2][2] * 0.015625f,
                                               oacc[n2][3] * 0.015625f);
        }
    }
}

extern "C" void kernel_launch(void* const* d_in, const int* in_sizes, int n_in,
                              void* d_out, int out_size) {
    const float* q = (const float*)d_in[0];
    const float* k = (const float*)d_in[1];
    const float* v = (const float*)d_in[2];
    float* o = (float*)d_out;

    convert_kv<<<512, 512>>>(k, v);

    cudaFuncSetAttribute(dot_relu_attn_v12,
                         cudaFuncAttributeMaxDynamicSharedMemorySize, SMEM_BYTES);
    dim3 grid(SEQ / BM, BH);
    dot_relu_attn_v12<<<grid, NTH, SMEM_BYTES>>>(q, o);
}

// round 16
// speedup vs baseline: 1.0569x; 1.0569x over previous
#include <cuda_runtime.h>
#include <cuda_fp16.h>
#include <cstdint>

// DotReluAttention: out = relu(Q @ K^T / 64) @ V ; B=2,H=8,S=4096,D=64 fp32.
// v13 = v11 base + (a) K/V images relaid so K fragments load as LDS.128 and
// V fragments as LDS.64 (hot-loop LDS issues halved), (b) 3-stage cp.async
// pipeline with ONE barrier per iteration. Arithmetic identical to v11.

#define SEQ 4096
#define HD  64
#define BM  256
#define BN  128
#define NTH 512
#define NITER (SEQ/BN)    // 32
#define NK16  (BN/16)     // 8
#define BH    16

// smem geometry
#define QSTR 40                 // Q staging row stride (words, startup only)
#define KSTRW 36                // K row stride (words) = 144B
#define VSTRW 136               // V uint2-row stride (words) = 544B
#define KWORDSW (BN*KSTRW)      // 4608 words
#define KTILEB  (BN*144)        // 18432 B
#define VTILEB  (32*544)        // 17408 B
#define BUFB    (KTILEB+VTILEB) // 35840 B
#define BUFW    (BUFB/4)        // 8960 words
#define SMEM_BYTES (3*BUFB)     // 107520

// pre-converted fp16 images
__device__ __align__(16) uint32_t g_K16[(size_t)BH*SEQ*32];       // 8MB
__device__ __align__(16) uint32_t g_V16[(size_t)BH*(SEQ/2)*64];   // 8MB

__device__ __forceinline__ uint32_t pack2(float a, float b) {
    __half2 h = __floats2half2_rn(a, b);
    return *reinterpret_cast<uint32_t*>(&h);
}
__device__ __forceinline__ void mma16(float* c, const uint32_t* a,
                                      uint32_t b0, uint32_t b1) {
    asm volatile(
        "mma.sync.aligned.m16n8k16.row.col.f32.f16.f16.f32 "
        "{%0,%1,%2,%3}, {%4,%5,%6,%7}, {%8,%9}, {%0,%1,%2,%3};\n"
        : "+f"(c[0]), "+f"(c[1]), "+f"(c[2]), "+f"(c[3])
        : "r"(a[0]), "r"(a[1]), "r"(a[2]), "r"(a[3]), "r"(b0), "r"(b1));
}
__device__ __forceinline__ int wpos(int w) {    // Q staging permute (unchanged)
    return (w & ~7) + 2 * (w & 3) + ((w & 4) >> 2);
}
__device__ __forceinline__ uint32_t smem_u32(const void* p) {
    uint32_t a;
    asm("{ .reg .u64 t; cvta.to.shared.u64 t, %1; cvt.u32.u64 %0, t; }" : "=r"(a) : "l"(p));
    return a;
}
#define CP16(dst, src) \
    asm volatile("cp.async.cg.shared.global [%0], [%1], 16;" :: "r"(dst), "l"(src) : "memory")
#define CP_COMMIT() asm volatile("cp.async.commit_group;" ::: "memory")
#define CP_WAIT(n)  asm volatile("cp.async.wait_group %0;" :: "n"(n) : "memory")

// ---------- kernel 1: K fp32 -> fp16, fragment-contiguous word order ----------
// row r, lane-group tig owns words tig*8..tig*8+7 = [kt0b0,kt0b1,...,kt3b1]
// word (kt,h) = pack(K[r][16kt+2tig+8h], K[r][16kt+2tig+8h+1])
__global__ __launch_bounds__(512)
void convert_k(const float* __restrict__ K) {
    int t = blockIdx.x * 512 + threadIdx.x;   // 262144
    int row = t >> 2, tig = t & 3;
    const float* src = K + (size_t)row * HD;
    uint32_t out[8];
    #pragma unroll
    for (int kt = 0; kt < 4; kt++)
        #pragma unroll
        for (int h = 0; h < 2; h++) {
            float2 f = *(const float2*)(src + 16 * kt + 2 * tig + 8 * h);
            out[kt * 2 + h] = pack2(f.x, f.y);
        }
    uint4* dst = (uint4*)(g_K16 + (size_t)row * 32 + tig * 8);
    dst[0] = make_uint4(out[0], out[1], out[2], out[3]);
    dst[1] = make_uint4(out[4], out[5], out[6], out[7]);
}

// ---------- kernel 2: V fp32 -> fp16, (b0,b1) adjacent uint2 rows ----------
// tile it, local row r (0..31): pair-row p0 = it*64 + 8*(r>>2) + (r&3)
// word[2n+0] = pack(V[2p0][n],   V[2p0+1][n])     (b0)
// word[2n+1] = pack(V[2p0+8][n], V[2p0+9][n])     (b1)
__global__ __launch_bounds__(512)
void convert_v(const float* __restrict__ V) {
    int t = blockIdx.x * 512 + threadIdx.x;   // 131072
    int row_id = t >> 3, j = t & 7;
    int bh = row_id >> 10;
    int it = (row_id >> 5) & 31;
    int r  = row_id & 31;
    int p0 = it * 64 + ((r >> 2) << 3) + (r & 3);
    const float* a0 = V + ((size_t)bh * SEQ + 2 * p0) * HD + j * 8;
    const float* a1 = a0 + HD;
    const float* b0 = a0 + 8 * HD;
    const float* b1 = b0 + HD;
    float4 A0[2] = {((const float4*)a0)[0], ((const float4*)a0)[1]};
    float4 A1[2] = {((const float4*)a1)[0], ((const float4*)a1)[1]};
    float4 B0[2] = {((const float4*)b0)[0], ((const float4*)b0)[1]};
    float4 B1[2] = {((const float4*)b1)[0], ((const float4*)b1)[1]};
    uint32_t* dst = g_V16 + (size_t)row_id * 128 + j * 16;
    const float* fa0 = (const float*)A0; const float* fa1 = (const float*)A1;
    const float* fb0 = (const float*)B0; const float* fb1 = (const float*)B1;
    #pragma unroll
    for (int i = 0; i < 8; i++) {
        dst[2 * i]     = pack2(fa0[i], fa1[i]);
        dst[2 * i + 1] = pack2(fb0[i], fb1[i]);
    }
}

// issue cp.async for one K/V tile into buffer at byte addr sbuf
__device__ __forceinline__ void issue_tile(int bh, int it, uint32_t sbuf, int tid) {
    const char* kbase = (const char*)(g_K16 + ((size_t)bh * SEQ + it * BN) * 32);
    #pragma unroll
    for (int i = 0; i < 2; i++) {
        int c = tid + i * NTH;                 // 1024 chunks of 16B
        CP16(sbuf + (c >> 3) * 144 + (c & 7) * 16, kbase + c * 16);
    }
    const char* vbase = (const char*)(g_V16 + ((size_t)(bh * 32 + it) * 32) * 128);
    #pragma unroll
    for (int i = 0; i < 2; i++) {
        int c = tid + i * NTH;                 // 1024 chunks of 16B
        CP16(sbuf + KTILEB + (c >> 5) * 544 + (c & 31) * 16, vbase + c * 16);
    }
}

// GEMM1 for one 16-col chunk: 4x LDS.128 total, 8 MMAs
__device__ __forceinline__ void g1_chunk(const uint32_t* kl,
                                         const uint32_t qa[4][4],
                                         int nk, float* s) {
    #pragma unroll
    for (int h = 0; h < 2; h++) {
        const uint32_t* p = kl + (2 * nk + h) * (8 * KSTRW);
        uint4 w0 = *(const uint4*)(p);
        uint4 w1 = *(const uint4*)(p + 4);
        float ta[4] = {0.f, 0.f, 0.f, 0.f};
        float tb[4] = {0.f, 0.f, 0.f, 0.f};
        mma16(ta, qa[0], w0.x, w0.y);
        mma16(tb, qa[1], w0.z, w0.w);
        mma16(ta, qa[2], w1.x, w1.y);
        mma16(tb, qa[3], w1.z, w1.w);
        s[4*h+0] = ta[0] + tb[0]; s[4*h+1] = ta[1] + tb[1];
        s[4*h+2] = ta[2] + tb[2]; s[4*h+3] = ta[3] + tb[3];
    }
}

// ---------- kernel 3: fused attention ----------
__global__ __launch_bounds__(NTH, 1)
void dot_relu_attn_v13(const float* __restrict__ Q, float* __restrict__ O) {
    extern __shared__ uint32_t sm[];
    const uint32_t sbase = smem_u32(sm);

    const int tid  = threadIdx.x;
    const int warp = tid >> 5;
    const int lane = tid & 31;
    const int gid  = lane >> 2;
    const int tig  = lane & 3;
    const int m0   = warp * 16;

    const int bh = blockIdx.y;
    const int qb = blockIdx.x * BM;
    const float* Qp = Q + ((size_t)bh * SEQ + qb) * HD;
    float*       Op = O + ((size_t)bh * SEQ + qb) * HD;

    // ---- Stage Q (one-time; unchanged v11 scheme) ----
    #pragma unroll
    for (int i = 0; i < 8; i++) {
        int lin = tid + i * NTH;
        int row = lin >> 4, c4 = lin & 15;
        float4 v = *(const float4*)(Qp + row * HD + c4 * 4);
        sm[row * QSTR + wpos(2 * c4)]     = pack2(v.x, v.y);
        sm[row * QSTR + wpos(2 * c4 + 1)] = pack2(v.z, v.w);
    }
    __syncthreads();
    uint32_t qa[4][4];
    #pragma unroll
    for (int kt = 0; kt < 4; kt++) {
        const uint32_t* p = &sm[(m0 + gid) * QSTR + kt * 8 + 2 * tig];
        uint2 lo = *(const uint2*)p;
        uint2 hi = *(const uint2*)(p + 8 * QSTR);
        qa[kt][0] = lo.x; qa[kt][1] = hi.x;
        qa[kt][2] = lo.y; qa[kt][3] = hi.y;
    }
    __syncthreads();   // staging done; buffers free

    float oacc[8][4];
    #pragma unroll
    for (int b = 0; b < 8; b++)
        #pragma unroll
        for (int c = 0; c < 4; c++) oacc[b][c] = 0.f;

    // prologue: tiles 0 and 1 in flight
    issue_tile(bh, 0, sbase,        tid); CP_COMMIT();
    issue_tile(bh, 1, sbase + BUFB, tid); CP_COMMIT();

    int cb = 0;
    #pragma unroll 1
    for (int it = 0; it < NITER; it++) {
        if (it + 1 < NITER) { CP_WAIT(1); } else { CP_WAIT(0); }
        __syncthreads();        // tile it visible; all warps done with it-1

        if (it + 2 < NITER) {
            int ib = cb + 2; if (ib >= 3) ib -= 3;
            issue_tile(bh, it + 2, sbase + ib * BUFB, tid);
            CP_COMMIT();
        }

        const uint32_t* kl = sm + cb * BUFW + gid * KSTRW + tig * 8;
        const uint32_t* vl = sm + cb * BUFW + KWORDSW + tig * VSTRW + gid * 2;

        // ---- software-pipelined chunk loop (constants fully unrolled) ----
        float scur[8];
        g1_chunk(kl, qa, 0, scur);
        #pragma unroll
        for (int nk = 0; nk < NK16; nk++) {
            float snxt[8];
            if (nk + 1 < NK16)
                g1_chunk(kl, qa, nk + 1, snxt);

            // relu + pack: GEMM1 C-fragment == GEMM2 A-fragment
            uint32_t pa[4];
            pa[0] = pack2(fmaxf(scur[0], 0.f), fmaxf(scur[1], 0.f));
            pa[1] = pack2(fmaxf(scur[2], 0.f), fmaxf(scur[3], 0.f));
            pa[2] = pack2(fmaxf(scur[4], 0.f), fmaxf(scur[5], 0.f));
            pa[3] = pack2(fmaxf(scur[6], 0.f), fmaxf(scur[7], 0.f));

            // GEMM2: (b0,b1) as single LDS.64 each, 8 independent accumulators
            const uint32_t* vb = vl + nk * (4 * VSTRW);
            #pragma unroll
            for (int n2 = 0; n2 < 8; n2++) {
                uint2 b = *(const uint2*)(vb + n2 * 16);
                mma16(oacc[n2], pa, b.x, b.y);
            }

            #pragma unroll
            for (int x = 0; x < 8; x++) scur[x] = snxt[x];
        }
        cb++; if (cb == 3) cb = 0;
    }

    // ---- Epilogue: O_out = O / 64 ----
    {
        float* r0 = Op + (size_t)(m0 + gid) * HD;
        float* r1 = r0 + 8 * HD;
        #pragma unroll
        for (int n2 = 0; n2 < 8; n2++) {
            int col = n2 * 8 + 2 * tig;
            *(float2*)(r0 + col) = make_float2(oacc[n2][0] * 0.015625f,
                                               oacc[n2][1] * 0.015625f);
            *(float2*)(r1 + col) = make_float2(oacc[n2][2] * 0.015625f,
                                               oacc[n2][3] * 0.015625f);
        }
    }
}

extern "C" void kernel_launch(void* const* d_in, const int* in_sizes, int n_in,
                              void* d_out, int out_size) {
    const float* q = (const float*)d_in[0];
    const float* k = (const float*)d_in[1];
    const float* v = (const float*)d_in[2];
    float* o = (float*)d_out;

    convert_k<<<512, 512>>>(k);
    convert_v<<<256, 512>>>(v);

    cudaFuncSetAttribute(dot_relu_attn_v13,
                         cudaFuncAttributeMaxDynamicSharedMemorySize, SMEM_BYTES);
    dim3 grid(SEQ / BM, BH);
    dot_relu_attn_v13<<<grid, NTH, SMEM_BYTES>>>(q, o);
}

// round 17
// speedup vs baseline: 1.0577x; 1.0008x over previous
#include <cuda_runtime.h>
#include <cuda_fp16.h>
#include <cstdint>

// DotReluAttention: out = relu(Q @ K^T / 64) @ V ; B=2,H=8,S=4096,D=64 fp32.
// v14 = v13 + kv-split-4: grid 16x16x4 CTAs (each does 1/4 of the kv range),
// flattening the 2.0-wave tail to 1.75 waves. Output accumulated with
// red.global.add.v2.f32 onto a zero-initialized d_out.

#define SEQ 4096
#define HD  64
#define BM  256
#define BN  128
#define NTH 512
#define NSPLIT 4
#define NITER (SEQ/BN/NSPLIT)   // 8 tiles per CTA
#define NK16  (BN/16)           // 8
#define BH    16

// smem geometry
#define QSTR 40                 // Q staging row stride (words, startup only)
#define KSTRW 36                // K row stride (words) = 144B
#define VSTRW 136               // V uint2-row stride (words) = 544B
#define KWORDSW (BN*KSTRW)      // 4608 words
#define KTILEB  (BN*144)        // 18432 B
#define VTILEB  (32*544)        // 17408 B
#define BUFB    (KTILEB+VTILEB) // 35840 B
#define BUFW    (BUFB/4)        // 8960 words
#define SMEM_BYTES (3*BUFB)     // 107520

// pre-converted fp16 images
__device__ __align__(16) uint32_t g_K16[(size_t)BH*SEQ*32];       // 8MB
__device__ __align__(16) uint32_t g_V16[(size_t)BH*(SEQ/2)*64];   // 8MB

__device__ __forceinline__ uint32_t pack2(float a, float b) {
    __half2 h = __floats2half2_rn(a, b);
    return *reinterpret_cast<uint32_t*>(&h);
}
__device__ __forceinline__ void mma16(float* c, const uint32_t* a,
                                      uint32_t b0, uint32_t b1) {
    asm volatile(
        "mma.sync.aligned.m16n8k16.row.col.f32.f16.f16.f32 "
        "{%0,%1,%2,%3}, {%4,%5,%6,%7}, {%8,%9}, {%0,%1,%2,%3};\n"
        : "+f"(c[0]), "+f"(c[1]), "+f"(c[2]), "+f"(c[3])
        : "r"(a[0]), "r"(a[1]), "r"(a[2]), "r"(a[3]), "r"(b0), "r"(b1));
}
__device__ __forceinline__ int wpos(int w) {
    return (w & ~7) + 2 * (w & 3) + ((w & 4) >> 2);
}
__device__ __forceinline__ uint32_t smem_u32(const void* p) {
    uint32_t a;
    asm("{ .reg .u64 t; cvta.to.shared.u64 t, %1; cvt.u32.u64 %0, t; }" : "=r"(a) : "l"(p));
    return a;
}
#define CP16(dst, src) \
    asm volatile("cp.async.cg.shared.global [%0], [%1], 16;" :: "r"(dst), "l"(src) : "memory")
#define CP_COMMIT() asm volatile("cp.async.commit_group;" ::: "memory")
#define CP_WAIT(n)  asm volatile("cp.async.wait_group %0;" :: "n"(n) : "memory")
#define REDV2(p, a, b) \
    asm volatile("red.global.add.v2.f32 [%0], {%1, %2};" :: "l"(p), "f"(a), "f"(b) : "memory")

// ---------- kernel 0: zero the output ----------
__global__ __launch_bounds__(512)
void zero_out(float4* __restrict__ o) {
    o[blockIdx.x * 512 + threadIdx.x] = make_float4(0.f, 0.f, 0.f, 0.f);
}

// ---------- kernel 1: K fp32 -> fp16, fragment-contiguous word order ----------
__global__ __launch_bounds__(512)
void convert_k(const float* __restrict__ K) {
    int t = blockIdx.x * 512 + threadIdx.x;   // 262144
    int row = t >> 2, tig = t & 3;
    const float* src = K + (size_t)row * HD;
    uint32_t out[8];
    #pragma unroll
    for (int kt = 0; kt < 4; kt++)
        #pragma unroll
        for (int h = 0; h < 2; h++) {
            float2 f = *(const float2*)(src + 16 * kt + 2 * tig + 8 * h);
            out[kt * 2 + h] = pack2(f.x, f.y);
        }
    uint4* dst = (uint4*)(g_K16 + (size_t)row * 32 + tig * 8);
    dst[0] = make_uint4(out[0], out[1], out[2], out[3]);
    dst[1] = make_uint4(out[4], out[5], out[6], out[7]);
}

// ---------- kernel 2: V fp32 -> fp16, (b0,b1) adjacent uint2 rows ----------
__global__ __launch_bounds__(512)
void convert_v(const float* __restrict__ V) {
    int t = blockIdx.x * 512 + threadIdx.x;   // 131072
    int row_id = t >> 3, j = t & 7;
    int bh = row_id >> 10;
    int it = (row_id >> 5) & 31;
    int r  = row_id & 31;
    int p0 = it * 64 + ((r >> 2) << 3) + (r & 3);
    const float* a0 = V + ((size_t)bh * SEQ + 2 * p0) * HD + j * 8;
    const float* a1 = a0 + HD;
    const float* b0 = a0 + 8 * HD;
    const float* b1 = b0 + HD;
    float4 A0[2] = {((const float4*)a0)[0], ((const float4*)a0)[1]};
    float4 A1[2] = {((const float4*)a1)[0], ((const float4*)a1)[1]};
    float4 B0[2] = {((const float4*)b0)[0], ((const float4*)b0)[1]};
    float4 B1[2] = {((const float4*)b1)[0], ((const float4*)b1)[1]};
    uint32_t* dst = g_V16 + (size_t)row_id * 128 + j * 16;
    const float* fa0 = (const float*)A0; const float* fa1 = (const float*)A1;
    const float* fb0 = (const float*)B0; const float* fb1 = (const float*)B1;
    #pragma unroll
    for (int i = 0; i < 8; i++) {
        dst[2 * i]     = pack2(fa0[i], fa1[i]);
        dst[2 * i + 1] = pack2(fb0[i], fb1[i]);
    }
}

// issue cp.async for one K/V tile (global tile index itg) into buffer sbuf
__device__ __forceinline__ void issue_tile(int bh, int itg, uint32_t sbuf, int tid) {
    const char* kbase = (const char*)(g_K16 + ((size_t)bh * SEQ + itg * BN) * 32);
    #pragma unroll
    for (int i = 0; i < 2; i++) {
        int c = tid + i * NTH;
        CP16(sbuf + (c >> 3) * 144 + (c & 7) * 16, kbase + c * 16);
    }
    const char* vbase = (const char*)(g_V16 + ((size_t)(bh * 32 + itg) * 32) * 128);
    #pragma unroll
    for (int i = 0; i < 2; i++) {
        int c = tid + i * NTH;
        CP16(sbuf + KTILEB + (c >> 5) * 544 + (c & 31) * 16, vbase + c * 16);
    }
}

// GEMM1 for one 16-col chunk: 4x LDS.128 total, 8 MMAs
__device__ __forceinline__ void g1_chunk(const uint32_t* kl,
                                         const uint32_t qa[4][4],
                                         int nk, float* s) {
    #pragma unroll
    for (int h = 0; h < 2; h++) {
        const uint32_t* p = kl + (2 * nk + h) * (8 * KSTRW);
        uint4 w0 = *(const uint4*)(p);
        uint4 w1 = *(const uint4*)(p + 4);
        float ta[4] = {0.f, 0.f, 0.f, 0.f};
        float tb[4] = {0.f, 0.f, 0.f, 0.f};
        mma16(ta, qa[0], w0.x, w0.y);
        mma16(tb, qa[1], w0.z, w0.w);
        mma16(ta, qa[2], w1.x, w1.y);
        mma16(tb, qa[3], w1.z, w1.w);
        s[4*h+0] = ta[0] + tb[0]; s[4*h+1] = ta[1] + tb[1];
        s[4*h+2] = ta[2] + tb[2]; s[4*h+3] = ta[3] + tb[3];
    }
}

// ---------- kernel 3: fused attention (one kv quarter per CTA) ----------
__global__ __launch_bounds__(NTH, 1)
void dot_relu_attn_v14(const float* __restrict__ Q, float* __restrict__ O) {
    extern __shared__ uint32_t sm[];
    const uint32_t sbase = smem_u32(sm);

    const int tid  = threadIdx.x;
    const int warp = tid >> 5;
    const int lane = tid & 31;
    const int gid  = lane >> 2;
    const int tig  = lane & 3;
    const int m0   = warp * 16;

    const int bh  = blockIdx.y;
    const int qb  = blockIdx.x * BM;
    const int it0 = blockIdx.z * NITER;       // kv quarter start tile
    const float* Qp = Q + ((size_t)bh * SEQ + qb) * HD;
    float*       Op = O + ((size_t)bh * SEQ + qb) * HD;

    // ---- Stage Q (one-time; staging overlaps the K/V buffers) ----
    #pragma unroll
    for (int i = 0; i < 8; i++) {
        int lin = tid + i * NTH;
        int row = lin >> 4, c4 = lin & 15;
        float4 v = *(const float4*)(Qp + row * HD + c4 * 4);
        sm[row * QSTR + wpos(2 * c4)]     = pack2(v.x, v.y);
        sm[row * QSTR + wpos(2 * c4 + 1)] = pack2(v.z, v.w);
    }
    __syncthreads();
    uint32_t qa[4][4];
    #pragma unroll
    for (int kt = 0; kt < 4; kt++) {
        const uint32_t* p = &sm[(m0 + gid) * QSTR + kt * 8 + 2 * tig];
        uint2 lo = *(const uint2*)p;
        uint2 hi = *(const uint2*)(p + 8 * QSTR);
        qa[kt][0] = lo.x; qa[kt][1] = hi.x;
        qa[kt][2] = lo.y; qa[kt][3] = hi.y;
    }
    __syncthreads();   // staging done; buffers free

    float oacc[8][4];
    #pragma unroll
    for (int b = 0; b < 8; b++)
        #pragma unroll
        for (int c = 0; c < 4; c++) oacc[b][c] = 0.f;

    // prologue: tiles it0, it0+1 in flight
    issue_tile(bh, it0,     sbase,        tid); CP_COMMIT();
    issue_tile(bh, it0 + 1, sbase + BUFB, tid); CP_COMMIT();

    int cb = 0;
    #pragma unroll 1
    for (int it = 0; it < NITER; it++) {
        if (it + 1 < NITER) { CP_WAIT(1); } else { CP_WAIT(0); }
        __syncthreads();        // tile it visible; all warps done with it-1

        if (it + 2 < NITER) {
            int ib = cb + 2; if (ib >= 3) ib -= 3;
            issue_tile(bh, it0 + it + 2, sbase + ib * BUFB, tid);
            CP_COMMIT();
        }

        const uint32_t* kl = sm + cb * BUFW + gid * KSTRW + tig * 8;
        const uint32_t* vl = sm + cb * BUFW + KWORDSW + tig * VSTRW + gid * 2;

        float scur[8];
        g1_chunk(kl, qa, 0, scur);
        #pragma unroll
        for (int nk = 0; nk < NK16; nk++) {
            float snxt[8];
            if (nk + 1 < NK16)
                g1_chunk(kl, qa, nk + 1, snxt);

            uint32_t pa[4];
            pa[0] = pack2(fmaxf(scur[0], 0.f), fmaxf(scur[1], 0.f));
            pa[1] = pack2(fmaxf(scur[2], 0.f), fmaxf(scur[3], 0.f));
            pa[2] = pack2(fmaxf(scur[4], 0.f), fmaxf(scur[5], 0.f));
            pa[3] = pack2(fmaxf(scur[6], 0.f), fmaxf(scur[7], 0.f));

            const uint32_t* vb = vl + nk * (4 * VSTRW);
            #pragma unroll
            for (int n2 = 0; n2 < 8; n2++) {
                uint2 b = *(const uint2*)(vb + n2 * 16);
                mma16(oacc[n2], pa, b.x, b.y);
            }

            #pragma unroll
            for (int x = 0; x < 8; x++) scur[x] = snxt[x];
        }
        cb++; if (cb == 3) cb = 0;
    }

    // ---- Epilogue: O += partial / 64 (red.global.add.v2.f32) ----
    {
        float* r0 = Op + (size_t)(m0 + gid) * HD;
        float* r1 = r0 + 8 * HD;
        #pragma unroll
        for (int n2 = 0; n2 < 8; n2++) {
            int col = n2 * 8 + 2 * tig;
            REDV2(r0 + col, oacc[n2][0] * 0.015625f, oacc[n2][1] * 0.015625f);
            REDV2(r1 + col, oacc[n2][2] * 0.015625f, oacc[n2][3] * 0.015625f);
        }
    }
}

extern "C" void kernel_launch(void* const* d_in, const int* in_sizes, int n_in,
                              void* d_out, int out_size) {
    const float* q = (const float*)d_in[0];
    const float* k = (const float*)d_in[1];
    const float* v = (const float*)d_in[2];
    float* o = (float*)d_out;

    zero_out<<<2048, 512>>>((float4*)o);       // 4.19M floats = 1.05M float4
    convert_k<<<512, 512>>>(k);
    convert_v<<<256, 512>>>(v);

    cudaFuncSetAttribute(dot_relu_attn_v14,
                         cudaFuncAttributeMaxDynamicSharedMemorySize, SMEM_BYTES);
    dim3 grid(SEQ / BM, BH, NSPLIT);
    dot_relu_attn_v14<<<grid, NTH, SMEM_BYTES>>>(q, o);
}